// round 15
// baseline (speedup 1.0000x reference)
#include <cuda_runtime.h>
#include <cstdint>

#define NATOMS   4096
#define BLOCK_SZ 512
#define BOXF     44.0f
#define INV_BOX  (1.0f / 44.0f)
#define CUT2     (17.5f * 17.5f)

#define T        256                        // tile size (atoms)
#define NTILE    (NATOMS / T)               // 16
#define NPAIR    (NTILE * (NTILE + 1) / 2)  // 136 tile CTAs
#define NRED     7                          // 6 force-reduce CTAs + 1 energy CTA
#define NCTA     (NPAIR + NRED)             // 143 <= 148 SMs -> single wave
#define TPB      512                        // 16 warps
#define NQUAD    (NATOMS * 3 / 4)           // 3072 float4s per slot

// deterministic scratch + completion signalling
__device__ float    g_fpart[NTILE * NATOMS * 3];   // [slot][atom][xyz]
__device__ float    g_ecta[NPAIR];
__device__ unsigned g_done  = 0;   // tile-CTA arrival counter
__device__ unsigned g_rdone = 0;   // reducer completion counter (last resets both)

__inline__ __device__ float warp_sum(float v) {
    #pragma unroll
    for (int o = 16; o > 0; o >>= 1) v += __shfl_down_sync(0xffffffffu, v, o);
    return v;
}

// one pair: accumulates energy, returns g*r components
__inline__ __device__ void pm(float dx, float dy, float dz,
                              float a, float c, float dd, float rh, float sg,
                              bool ok0,
                              float& en, float& gx, float& gy, float& gz)
{
    dx -= rintf(dx * INV_BOX) * BOXF;
    dy -= rintf(dy * INV_BOX) * BOXF;
    dz -= rintf(dz * INV_BOX) * BOXF;
    const float r2 = fmaf(dx, dx, fmaf(dy, dy, dz * dz));

    const bool  ok = ok0 && (r2 < CUT2);
    const float we = ok ? 1.0f : 0.0f;
    const float wf = (ok && r2 > 1.0f) ? 1.0f : 0.0f;

    const float r2c  = fmaxf(r2, 1.0f);
    const float dinv = rsqrtf(r2c);
    const float dij  = r2c * dinv;

    const float invrh = __fdividef(1.0f, rh);
    const float e     = __expf((sg - dij) * invrh);

    const float inv2 = dinv * dinv;
    const float inv6 = inv2 * inv2 * inv2;
    const float inv8 = inv6 * inv2;

    const float ae = a * e;
    const float pe = fmaf(dd, inv8, fmaf(-c, inv6, ae));
    en = fmaf(we, pe, en);

    float g = fmaf(6.0f * c, inv8,
                   fmaf(-8.0f * dd, inv8 * inv2,
                        -(ae * invrh) * dinv));
    g *= wf;
    gx = g * dx; gy = g * dy; gz = g * dz;
}

#define QUAD(P4A, P4C, P4D, P4R, P4S, CB)                                         \
    {                                                                              \
        float gx, gy, gz;                                                          \
        pm(xi - xj[CB+0], yi - yj[CB+0], zi - zj[CB+0],                            \
           P4A.x, P4C.x, P4D.x, P4R.x, P4S.x,                                      \
           (dloc != (CB+0)) && (!DIAG || irel < (CB+0)), en, gx, gy, gz);          \
        rx += gx; ry += gy; rz += gz;                                              \
        fjx[CB+0] -= gx; fjy[CB+0] -= gy; fjz[CB+0] -= gz;                         \
        pm(xi - xj[CB+1], yi - yj[CB+1], zi - zj[CB+1],                            \
           P4A.y, P4C.y, P4D.y, P4R.y, P4S.y,                                      \
           (dloc != (CB+1)) && (!DIAG || irel < (CB+1)), en, gx, gy, gz);          \
        rx += gx; ry += gy; rz += gz;                                              \
        fjx[CB+1] -= gx; fjy[CB+1] -= gy; fjz[CB+1] -= gz;                         \
        pm(xi - xj[CB+2], yi - yj[CB+2], zi - zj[CB+2],                            \
           P4A.z, P4C.z, P4D.z, P4R.z, P4S.z,                                      \
           (dloc != (CB+2)) && (!DIAG || irel < (CB+2)), en, gx, gy, gz);          \
        rx += gx; ry += gy; rz += gz;                                              \
        fjx[CB+2] -= gx; fjy[CB+2] -= gy; fjz[CB+2] -= gz;                         \
        pm(xi - xj[CB+3], yi - yj[CB+3], zi - zj[CB+3],                            \
           P4A.w, P4C.w, P4D.w, P4R.w, P4S.w,                                      \
           (dloc != (CB+3)) && (!DIAG || irel < (CB+3)), en, gx, gy, gz);          \
        rx += gx; ry += gy; rz += gz;                                              \
        fjx[CB+3] -= gx; fjy[CB+3] -= gy; fjz[CB+3] -= gz;                         \
    }

template<bool DIAG>
__device__ __forceinline__ void tile_body(
    int ti, int tj, int bidx,
    const float* __restrict__ coords,
    const float* __restrict__ A, const float* __restrict__ C,
    const float* __restrict__ D, const float* __restrict__ RHO,
    const float* __restrict__ SIG)
{
    const int t    = threadIdx.x;
    const int lane = t & 31;
    const int w    = t >> 5;                 // warp 0..15

    const int jc0 = 8 * lane;
    const int jg0 = tj * T + jc0;
    const float wbase = ((ti >> 1) == (tj >> 1)) ? 1.0f : 2.0f;

    float xj[8], yj[8], zj[8];
    {
        const float4* cf = (const float4*)(coords + 3 * (size_t)jg0);
        const float4 q0 = __ldg(cf + 0), q1 = __ldg(cf + 1), q2 = __ldg(cf + 2);
        const float4 q3 = __ldg(cf + 3), q4 = __ldg(cf + 4), q5 = __ldg(cf + 5);
        xj[0]=q0.x; yj[0]=q0.y; zj[0]=q0.z;  xj[1]=q0.w; yj[1]=q1.x; zj[1]=q1.y;
        xj[2]=q1.z; yj[2]=q1.w; zj[2]=q2.x;  xj[3]=q2.y; yj[3]=q2.z; zj[3]=q2.w;
        xj[4]=q3.x; yj[4]=q3.y; zj[4]=q3.z;  xj[5]=q3.w; yj[5]=q4.x; zj[5]=q4.y;
        xj[6]=q4.z; yj[6]=q4.w; zj[6]=q5.x;  xj[7]=q5.y; yj[7]=q5.z; zj[7]=q5.w;
    }
    const int locj0 = jg0 & (BLOCK_SZ - 1);

    __shared__ float frow[T][3];
    __shared__ float fcolp[16][T * 3];
    __shared__ float esm[TPB / 32];

    float fjx[8], fjy[8], fjz[8];
    #pragma unroll
    for (int c = 0; c < 8; ++c) { fjx[c] = 0.f; fjy[c] = 0.f; fjz[c] = 0.f; }
    float en = 0.f;

    const size_t rowstart = (size_t)(ti * T) * NATOMS + tj * T + jc0;

    #pragma unroll 2
    for (int s = 0; s < T / 16; ++s) {
        const int i  = s * 16 + w;
        const int ig = ti * T + i;
        const size_t off = rowstart + (size_t)i * NATOMS;

        const float4 aA = __ldg((const float4*)(A   + off));
        const float4 aB = __ldg((const float4*)(A   + off + 4));
        const float4 cA = __ldg((const float4*)(C   + off));
        const float4 cB = __ldg((const float4*)(C   + off + 4));
        const float4 dA = __ldg((const float4*)(D   + off));
        const float4 dB = __ldg((const float4*)(D   + off + 4));
        const float4 rA = __ldg((const float4*)(RHO + off));
        const float4 rB = __ldg((const float4*)(RHO + off + 4));
        const float4 sA = __ldg((const float4*)(SIG + off));
        const float4 sB = __ldg((const float4*)(SIG + off + 4));

        const float xi = __ldg(&coords[3 * ig + 0]);
        const float yi = __ldg(&coords[3 * ig + 1]);
        const float zi = __ldg(&coords[3 * ig + 2]);

        const int dloc = (ig & (BLOCK_SZ - 1)) - locj0;
        const int irel = i - jc0;

        float rx = 0.f, ry = 0.f, rz = 0.f;
        QUAD(aA, cA, dA, rA, sA, 0)
        QUAD(aB, cB, dB, rB, sB, 4)

        rx = warp_sum(rx); ry = warp_sum(ry); rz = warp_sum(rz);
        if (lane == 0) { frow[i][0] = rx; frow[i][1] = ry; frow[i][2] = rz; }
    }

    {
        float* cp = &fcolp[w][jc0 * 3];
        #pragma unroll
        for (int c = 0; c < 8; ++c) {
            cp[3 * c + 0] = fjx[c];
            cp[3 * c + 1] = fjy[c];
            cp[3 * c + 2] = fjz[c];
        }
    }

    en = warp_sum(en);
    if (lane == 0) esm[w] = en;
    __syncthreads();

    if (t < T) {
        float rx = frow[t][0], ry = frow[t][1], rz = frow[t][2];
        if (DIAG) {
            #pragma unroll
            for (int ww = 0; ww < 16; ++ww) {
                rx += fcolp[ww][t * 3 + 0];
                ry += fcolp[ww][t * 3 + 1];
                rz += fcolp[ww][t * 3 + 2];
            }
        }
        float* dst = g_fpart + ((size_t)tj * NATOMS + ti * T + t) * 3;
        dst[0] = wbase * rx; dst[1] = wbase * ry; dst[2] = wbase * rz;
    } else if (!DIAG) {
        const int c = t - T;
        float cx = 0.f, cy = 0.f, cz = 0.f;
        #pragma unroll
        for (int ww = 0; ww < 16; ++ww) {
            cx += fcolp[ww][c * 3 + 0];
            cy += fcolp[ww][c * 3 + 1];
            cz += fcolp[ww][c * 3 + 2];
        }
        float* dst = g_fpart + ((size_t)ti * NATOMS + tj * T + c) * 3;
        dst[0] = wbase * cx; dst[1] = wbase * cy; dst[2] = wbase * cz;
    }

    if (t < 32) {
        float v = (t < TPB / 32) ? esm[t] : 0.f;
        v = warp_sum(v);
        if (t == 0) g_ecta[bidx] = wbase * v;
    }

    // publish + arrive
    __syncthreads();
    if (t == 0) {
        __threadfence();
        atomicAdd(&g_done, 1u);
    }
}

__global__ __launch_bounds__(TPB)
void bmh_fused_kernel(const float* __restrict__ coords,
                      const float* __restrict__ A,
                      const float* __restrict__ C,
                      const float* __restrict__ D,
                      const float* __restrict__ RHO,
                      const float* __restrict__ SIG,
                      float* __restrict__ out)
{
    const int bid = blockIdx.x;
    const int t   = threadIdx.x;

    if (bid < NPAIR) {
        // ---- tile work ----
        int k = bid, ti = 0, rem = NTILE;
        while (k >= rem) { k -= rem; ++ti; --rem; }
        const int tj = ti + k;
        if (ti == tj)
            tile_body<true >(ti, tj, bid, coords, A, C, D, RHO, SIG);
        else
            tile_body<false>(ti, tj, bid, coords, A, C, D, RHO, SIG);
        return;
    }

    // ---- dedicated reducer CTAs (parked on otherwise-idle SMs) ----
    const int b = bid - NPAIR;                // 0..6

    if (t == 0) {
        // poll with plain volatile loads (7 pollers total — negligible traffic)
        while (*((volatile unsigned*)&g_done) < (unsigned)NPAIR) __nanosleep(128);
    }
    __syncthreads();
    __threadfence();                           // acquire before reading partials

    if (b < 6) {
        const int q = b * TPB + t;             // 0..3071 float4 quads
        const float4* fp = (const float4*)g_fpart;
        float sx = 0.f, sy = 0.f, sz = 0.f, sw = 0.f;
        #pragma unroll
        for (int p = 0; p < NTILE; ++p) {
            const float4 v = fp[(size_t)p * NQUAD + q];   // 16 independent loads, L2-hot
            sx += v.x; sy += v.y; sz += v.z; sw += v.w;
        }
        float* dst = out + 1 + q * 4;
        dst[0] = sx; dst[1] = sy; dst[2] = sz; dst[3] = sw;
    } else {
        // energy: fixed-order double sum over 136 CTA partials
        double s = 0.0;
        for (int k2 = t; k2 < NPAIR; k2 += TPB) s += (double)g_ecta[k2];
        __shared__ double sd[TPB];
        sd[t] = s;
        __syncthreads();
        #pragma unroll
        for (int o = TPB / 2; o > 0; o >>= 1) {
            if (t < o) sd[t] += sd[t + o];
            __syncthreads();
        }
        if (t == 0) out[0] = (float)sd[0];
    }

    // replay-safe reset: last reducer (all g_done reads already happened) clears both
    __syncthreads();
    if (t == 0) {
        __threadfence();
        const unsigned r = atomicAdd(&g_rdone, 1u);
        if (r == NRED - 1) {
            g_rdone = 0;
            g_done  = 0;
            __threadfence();
        }
    }
}

extern "C" void kernel_launch(void* const* d_in, const int* in_sizes, int n_in,
                              void* d_out, int out_size)
{
    const float* coords = (const float*)d_in[0];
    // d_in[1] = q (computed-but-unused upstream; faithfully ignored)
    const float* A   = (const float*)d_in[2];
    const float* C   = (const float*)d_in[3];
    const float* D   = (const float*)d_in[4];
    const float* RHO = (const float*)d_in[5];
    const float* SIG = (const float*)d_in[6];
    float* out = (float*)d_out;

    bmh_fused_kernel<<<NCTA, TPB>>>(coords, A, C, D, RHO, SIG, out);
}

// round 16
// speedup vs baseline: 1.1040x; 1.1040x over previous
#include <cuda_runtime.h>
#include <cstdint>

#define NATOMS   4096
#define BLOCK_SZ 512
#define BOXF     44.0f
#define INV_BOX  (1.0f / 44.0f)
#define CUT2     (17.5f * 17.5f)

#define T        256                        // tile size (atoms)
#define NTILE    (NATOMS / T)               // 16
#define NPAIR    (NTILE * (NTILE + 1) / 2)  // 136 CTAs -> single wave
#define TPB      512                        // 16 warps
#define NQUAD    (NATOMS * 3 / 4)           // 3072 float4s per slot

// per-warp double-buffered stage: 2 stages x 5 params x 256 floats
#define STG_FLOATS (5 * T)                  // 1280 floats per stage
#define WBUF_FLOATS (2 * STG_FLOATS)        // 2560 floats per warp
#define SBUF_FLOATS (16 * WBUF_FLOATS)      // 40960 floats = 160 KB
#define SMEM_FLOATS (SBUF_FLOATS + 16 * (T * 3) + T * 3 + 16)
#define SMEM_BYTES  (SMEM_FLOATS * 4)       // 216,128 B

// deterministic scratch
__device__ float g_fpart[NTILE * NATOMS * 3];   // [slot][atom][xyz]
__device__ float g_ecta[NPAIR];

__inline__ __device__ float warp_sum(float v) {
    #pragma unroll
    for (int o = 16; o > 0; o >>= 1) v += __shfl_down_sync(0xffffffffu, v, o);
    return v;
}

__inline__ __device__ uint32_t su32(const void* p) {
    uint32_t a;
    asm("{ .reg .u64 t; cvta.to.shared.u64 t, %1; cvt.u32.u64 %0, t; }" : "=r"(a) : "l"(p));
    return a;
}

__device__ __forceinline__ void cp16(uint32_t s, const float* g) {
    asm volatile("cp.async.cg.shared.global [%0], [%1], 16;" :: "r"(s), "l"(g));
}

// stage one row (5 params x 1KB); lane copies its own 32B of each param row
__device__ __forceinline__ void stage_row(
    const float* __restrict__ A, const float* __restrict__ C,
    const float* __restrict__ D, const float* __restrict__ RHO,
    const float* __restrict__ SIG,
    size_t rowf /* float index of row start incl. tj*T */,
    uint32_t sb /* stage base (u32 smem) */, int lane)
{
    const size_t o = rowf + lane * 8;
    const uint32_t d = sb + lane * 32;
    cp16(d,                 A   + o); cp16(d + 16,              A   + o + 4);
    cp16(d + 1024,          C   + o); cp16(d + 1024 + 16,       C   + o + 4);
    cp16(d + 2048,          D   + o); cp16(d + 2048 + 16,       D   + o + 4);
    cp16(d + 3072,          RHO + o); cp16(d + 3072 + 16,       RHO + o + 4);
    cp16(d + 4096,          SIG + o); cp16(d + 4096 + 16,       SIG + o + 4);
    asm volatile("cp.async.commit_group;" ::: "memory");
}

// one pair: accumulates energy, returns g*r components
__inline__ __device__ void pm(float dx, float dy, float dz,
                              float a, float c, float dd, float rh, float sg,
                              bool ok0,
                              float& en, float& gx, float& gy, float& gz)
{
    dx -= rintf(dx * INV_BOX) * BOXF;
    dy -= rintf(dy * INV_BOX) * BOXF;
    dz -= rintf(dz * INV_BOX) * BOXF;
    const float r2 = fmaf(dx, dx, fmaf(dy, dy, dz * dz));

    const bool  ok = ok0 && (r2 < CUT2);
    const float we = ok ? 1.0f : 0.0f;
    const float wf = (ok && r2 > 1.0f) ? 1.0f : 0.0f;

    const float r2c  = fmaxf(r2, 1.0f);
    const float dinv = rsqrtf(r2c);
    const float dij  = r2c * dinv;

    const float invrh = __fdividef(1.0f, rh);
    const float e     = __expf((sg - dij) * invrh);

    const float inv2 = dinv * dinv;
    const float inv6 = inv2 * inv2 * inv2;
    const float inv8 = inv6 * inv2;

    const float ae = a * e;
    const float pe = fmaf(dd, inv8, fmaf(-c, inv6, ae));
    en = fmaf(we, pe, en);

    float g = fmaf(6.0f * c, inv8,
                   fmaf(-8.0f * dd, inv8 * inv2,
                        -(ae * invrh) * dinv));
    g *= wf;
    gx = g * dx; gy = g * dy; gz = g * dz;
}

#define QUAD(P4A, P4C, P4D, P4R, P4S, CB)                                         \
    {                                                                              \
        float gx, gy, gz;                                                          \
        pm(xi - xj[CB+0], yi - yj[CB+0], zi - zj[CB+0],                            \
           P4A.x, P4C.x, P4D.x, P4R.x, P4S.x,                                      \
           (dloc != (CB+0)) && (!DIAG || irel < (CB+0)), en, gx, gy, gz);          \
        rx += gx; ry += gy; rz += gz;                                              \
        fjx[CB+0] -= gx; fjy[CB+0] -= gy; fjz[CB+0] -= gz;                         \
        pm(xi - xj[CB+1], yi - yj[CB+1], zi - zj[CB+1],                            \
           P4A.y, P4C.y, P4D.y, P4R.y, P4S.y,                                      \
           (dloc != (CB+1)) && (!DIAG || irel < (CB+1)), en, gx, gy, gz);          \
        rx += gx; ry += gy; rz += gz;                                              \
        fjx[CB+1] -= gx; fjy[CB+1] -= gy; fjz[CB+1] -= gz;                         \
        pm(xi - xj[CB+2], yi - yj[CB+2], zi - zj[CB+2],                            \
           P4A.z, P4C.z, P4D.z, P4R.z, P4S.z,                                      \
           (dloc != (CB+2)) && (!DIAG || irel < (CB+2)), en, gx, gy, gz);          \
        rx += gx; ry += gy; rz += gz;                                              \
        fjx[CB+2] -= gx; fjy[CB+2] -= gy; fjz[CB+2] -= gz;                         \
        pm(xi - xj[CB+3], yi - yj[CB+3], zi - zj[CB+3],                            \
           P4A.w, P4C.w, P4D.w, P4R.w, P4S.w,                                      \
           (dloc != (CB+3)) && (!DIAG || irel < (CB+3)), en, gx, gy, gz);          \
        rx += gx; ry += gy; rz += gz;                                              \
        fjx[CB+3] -= gx; fjy[CB+3] -= gy; fjz[CB+3] -= gz;                         \
    }

template<bool DIAG>
__device__ __forceinline__ void tile_body(
    int ti, int tj, int bidx,
    const float* __restrict__ coords,
    const float* __restrict__ A, const float* __restrict__ C,
    const float* __restrict__ D, const float* __restrict__ RHO,
    const float* __restrict__ SIG)
{
    extern __shared__ float smem_dyn[];
    float* sbuf  = smem_dyn;                        // [16 warps][2][5][256]
    float* fcolp = smem_dyn + SBUF_FLOATS;          // [16][768]
    float* frow  = fcolp + 16 * (T * 3);            // [256][3]
    float* esm   = frow + T * 3;                    // [16]

    const int t    = threadIdx.x;
    const int lane = t & 31;
    const int w    = t >> 5;                 // warp 0..15

    const int jc0 = 8 * lane;
    const int jg0 = tj * T + jc0;
    const float wbase = ((ti >> 1) == (tj >> 1)) ? 1.0f : 2.0f;

    // column coords: direct float4 extraction
    float xj[8], yj[8], zj[8];
    {
        const float4* cf = (const float4*)(coords + 3 * (size_t)jg0);
        const float4 q0 = __ldg(cf + 0), q1 = __ldg(cf + 1), q2 = __ldg(cf + 2);
        const float4 q3 = __ldg(cf + 3), q4 = __ldg(cf + 4), q5 = __ldg(cf + 5);
        xj[0]=q0.x; yj[0]=q0.y; zj[0]=q0.z;  xj[1]=q0.w; yj[1]=q1.x; zj[1]=q1.y;
        xj[2]=q1.z; yj[2]=q1.w; zj[2]=q2.x;  xj[3]=q2.y; yj[3]=q2.z; zj[3]=q2.w;
        xj[4]=q3.x; yj[4]=q3.y; zj[4]=q3.z;  xj[5]=q3.w; yj[5]=q4.x; zj[5]=q4.y;
        xj[6]=q4.z; yj[6]=q4.w; zj[6]=q5.x;  xj[7]=q5.y; yj[7]=q5.z; zj[7]=q5.w;
    }
    const int locj0 = jg0 & (BLOCK_SZ - 1);

    float fjx[8], fjy[8], fjz[8];
    #pragma unroll
    for (int c = 0; c < 8; ++c) { fjx[c] = 0.f; fjy[c] = 0.f; fjz[c] = 0.f; }
    float en = 0.f;

    // per-warp stage buffers (private: no cross-warp sync in main loop)
    float* wbuf = sbuf + w * WBUF_FLOATS;
    const uint32_t sb0 = su32(wbuf);
    const uint32_t sb1 = su32(wbuf + STG_FLOATS);

    // row s for warp w: global row ti*T + s*16 + w; float index incl column base
    const size_t row0 = (size_t)(ti * T + w) * NATOMS + tj * T;

    // prologue: stage row-iter 0
    stage_row(A, C, D, RHO, SIG, row0, sb0, lane);

    #pragma unroll 1
    for (int s = 0; s < T / 16; ++s) {
        // prefetch next row into alternate buffer (fire-and-forget)
        if (s + 1 < T / 16) {
            stage_row(A, C, D, RHO, SIG, row0 + (size_t)(s + 1) * 16 * NATOMS,
                      (s + 1) & 1 ? sb1 : sb0, lane);
            asm volatile("cp.async.wait_group 1;" ::: "memory");   // stage s ready
        } else {
            asm volatile("cp.async.wait_group 0;" ::: "memory");
        }

        const int i  = s * 16 + w;
        const int ig = ti * T + i;
        const float* bp = (s & 1) ? (wbuf + STG_FLOATS) : wbuf;   // param 0 base
        const float* lp = bp + jc0;                               // lane's 8 cols

        const float4 aA = *(const float4*)(lp + 0 * T);
        const float4 aB = *(const float4*)(lp + 0 * T + 4);
        const float4 cA = *(const float4*)(lp + 1 * T);
        const float4 cB = *(const float4*)(lp + 1 * T + 4);
        const float4 dA = *(const float4*)(lp + 2 * T);
        const float4 dB = *(const float4*)(lp + 2 * T + 4);
        const float4 rA = *(const float4*)(lp + 3 * T);
        const float4 rB = *(const float4*)(lp + 3 * T + 4);
        const float4 sA = *(const float4*)(lp + 4 * T);
        const float4 sB = *(const float4*)(lp + 4 * T + 4);

        const float xi = __ldg(&coords[3 * ig + 0]);
        const float yi = __ldg(&coords[3 * ig + 1]);
        const float zi = __ldg(&coords[3 * ig + 2]);

        const int dloc = (ig & (BLOCK_SZ - 1)) - locj0;
        const int irel = i - jc0;

        float rx = 0.f, ry = 0.f, rz = 0.f;
        QUAD(aA, cA, dA, rA, sA, 0)
        QUAD(aB, cB, dB, rB, sB, 4)

        rx = warp_sum(rx); ry = warp_sum(ry); rz = warp_sum(rz);
        if (lane == 0) { frow[i * 3 + 0] = rx; frow[i * 3 + 1] = ry; frow[i * 3 + 2] = rz; }
    }

    // stash per-warp column partials
    {
        float* cp = fcolp + w * (T * 3) + jc0 * 3;
        #pragma unroll
        for (int c = 0; c < 8; ++c) {
            cp[3 * c + 0] = fjx[c];
            cp[3 * c + 1] = fjy[c];
            cp[3 * c + 2] = fjz[c];
        }
    }

    en = warp_sum(en);
    if (lane == 0) esm[w] = en;
    __syncthreads();

    if (t < T) {
        float rx = frow[t * 3 + 0], ry = frow[t * 3 + 1], rz = frow[t * 3 + 2];
        if (DIAG) {
            #pragma unroll
            for (int ww = 0; ww < 16; ++ww) {
                rx += fcolp[ww * (T * 3) + t * 3 + 0];
                ry += fcolp[ww * (T * 3) + t * 3 + 1];
                rz += fcolp[ww * (T * 3) + t * 3 + 2];
            }
        }
        float* dst = g_fpart + ((size_t)tj * NATOMS + ti * T + t) * 3;
        dst[0] = wbase * rx; dst[1] = wbase * ry; dst[2] = wbase * rz;
    } else if (!DIAG) {
        const int c = t - T;
        float cx = 0.f, cy = 0.f, cz = 0.f;
        #pragma unroll
        for (int ww = 0; ww < 16; ++ww) {
            cx += fcolp[ww * (T * 3) + c * 3 + 0];
            cy += fcolp[ww * (T * 3) + c * 3 + 1];
            cz += fcolp[ww * (T * 3) + c * 3 + 2];
        }
        float* dst = g_fpart + ((size_t)ti * NATOMS + tj * T + c) * 3;
        dst[0] = wbase * cx; dst[1] = wbase * cy; dst[2] = wbase * cz;
    }

    if (t < 32) {
        float v = (t < TPB / 32) ? esm[t] : 0.f;
        v = warp_sum(v);
        if (t == 0) g_ecta[bidx] = wbase * v;
    }
}

__global__ __launch_bounds__(TPB)
void bmh_tile_kernel(const float* __restrict__ coords,
                     const float* __restrict__ A,
                     const float* __restrict__ C,
                     const float* __restrict__ D,
                     const float* __restrict__ RHO,
                     const float* __restrict__ SIG)
{
    int k = blockIdx.x, ti = 0, rem = NTILE;
    while (k >= rem) { k -= rem; ++ti; --rem; }
    const int tj = ti + k;

    if (ti == tj)
        tile_body<true >(ti, tj, blockIdx.x, coords, A, C, D, RHO, SIG);
    else
        tile_body<false>(ti, tj, blockIdx.x, coords, A, C, D, RHO, SIG);
}

// reduce: 24 CTAs x 128 threads + 1 energy CTA (proven minimal tail)
#define RTPB 128

__global__ __launch_bounds__(RTPB)
void bmh_reduce_kernel(float* __restrict__ out)
{
    const int tid = threadIdx.x;
    const int b   = blockIdx.x;

    if (b < 24) {
        const int q = b * RTPB + tid;         // 0..3071
        const float4* fp = (const float4*)g_fpart;
        float sx = 0.f, sy = 0.f, sz = 0.f, sw = 0.f;
        #pragma unroll
        for (int p = 0; p < NTILE; ++p) {
            const float4 v = fp[(size_t)p * NQUAD + q];
            sx += v.x; sy += v.y; sz += v.z; sw += v.w;
        }
        float* dst = out + 1 + q * 4;
        dst[0] = sx; dst[1] = sy; dst[2] = sz; dst[3] = sw;
    } else {
        double s = 0.0;
        for (int k2 = tid; k2 < NPAIR; k2 += RTPB) s += (double)g_ecta[k2];
        __shared__ double sd[RTPB];
        sd[tid] = s;
        __syncthreads();
        #pragma unroll
        for (int o = RTPB / 2; o > 0; o >>= 1) {
            if (tid < o) sd[tid] += sd[tid + o];
            __syncthreads();
        }
        if (tid == 0) out[0] = (float)sd[0];
    }
}

extern "C" void kernel_launch(void* const* d_in, const int* in_sizes, int n_in,
                              void* d_out, int out_size)
{
    const float* coords = (const float*)d_in[0];
    // d_in[1] = q (computed-but-unused upstream; faithfully ignored)
    const float* A   = (const float*)d_in[2];
    const float* C   = (const float*)d_in[3];
    const float* D   = (const float*)d_in[4];
    const float* RHO = (const float*)d_in[5];
    const float* SIG = (const float*)d_in[6];
    float* out = (float*)d_out;

    cudaFuncSetAttribute(bmh_tile_kernel,
                         cudaFuncAttributeMaxDynamicSharedMemorySize, SMEM_BYTES);
    bmh_tile_kernel<<<NPAIR, TPB, SMEM_BYTES>>>(coords, A, C, D, RHO, SIG);
    bmh_reduce_kernel<<<25, RTPB>>>(out);
}